// round 1
// baseline (speedup 1.0000x reference)
#include <cuda_runtime.h>

// Problem constants
#define B_ 16
#define T_ 64
#define E_ 2
#define F_ 64     // F_in == F_out
#define N_ 128
#define TAPSZ (B_*T_*E_*F_*N_)   // 16,777,216 floats = 64 MB

// Scratch for the three shifted/diffused taps A1,A2,A3 (tap0 is x itself).
__device__ float g_tap[3][TAPSZ];

// ----------------------------------------------------------------------------
// Diffusion pass: out[b,t,e] = in[b,t-1,(e)] @ S[b,t,e]   ([64,128]@[128,128])
//   pass 0: in = x[b,t-1]        (broadcast over e)  -> g_tap[0]
//   pass 1: in = g_tap[0][b,t-1,e]                   -> g_tap[1]
//   pass 2: in = g_tap[1][b,t-1,e]                   -> g_tap[2]
// t == 0 writes zeros (time shift pads with a zero row).
// ----------------------------------------------------------------------------
__global__ __launch_bounds__(256) void diffuse_kernel(
    const float* __restrict__ x, const float* __restrict__ S, int pass)
{
    int idx = blockIdx.x;
    int e = idx & 1;
    int t = (idx >> 1) & (T_ - 1);
    int b = idx >> 7;

    float* out = &g_tap[pass][(((b * T_ + t) * E_ + e) * F_) * N_];

    int tid = threadIdx.x;
    int tc = tid & 15;    // column group: cols tc*8 .. tc*8+7
    int tr = tid >> 4;    // row group:    rows tr*4 .. tr*4+3

    if (t == 0) {
        #pragma unroll
        for (int r = 0; r < 4; r++) {
            float4 z4 = {0.f, 0.f, 0.f, 0.f};
            *(float4*)&out[(tr * 4 + r) * N_ + tc * 8]     = z4;
            *(float4*)&out[(tr * 4 + r) * N_ + tc * 8 + 4] = z4;
        }
        return;
    }

    const float* in = (pass == 0)
        ? x + ((b * T_ + (t - 1)) * F_) * N_
        : &g_tap[pass - 1][(((b * T_ + (t - 1)) * E_ + e) * F_) * N_];
    const float* Sp = S + (((b * T_ + t) * E_ + e) * N_) * N_;

    __shared__ float As[F_][33];        // 64 x 32 chunk of A (+1 pad: conflict-free)
    __shared__ float Ss[32][N_ + 4];    // 32 x 128 chunk of S (+4 pad: keeps 16B align)

    float acc[4][8];
    #pragma unroll
    for (int r = 0; r < 4; r++)
        #pragma unroll
        for (int c = 0; c < 8; c++) acc[r][c] = 0.f;

    for (int kc = 0; kc < 4; kc++) {
        // Load A chunk: all 64 rows, cols kc*32..+31 (coalesced 128B rows)
        {
            int c = tid & 31, f0 = tid >> 5;
            #pragma unroll
            for (int i = 0; i < 8; i++)
                As[f0 + i * 8][c] = in[(f0 + i * 8) * N_ + kc * 32 + c];
        }
        // Load S chunk: rows kc*32..+31, all 128 cols (coalesced)
        {
            int c = tid & 127, j0 = tid >> 7;
            #pragma unroll
            for (int i = 0; i < 16; i++)
                Ss[j0 + i * 2][c] = Sp[(kc * 32 + j0 + i * 2) * N_ + c];
        }
        __syncthreads();

        #pragma unroll
        for (int kk = 0; kk < 32; kk++) {
            float a0 = As[tr * 4 + 0][kk];
            float a1 = As[tr * 4 + 1][kk];
            float a2 = As[tr * 4 + 2][kk];
            float a3 = As[tr * 4 + 3][kk];
            float4 s0 = *(const float4*)&Ss[kk][tc * 8];
            float4 s1 = *(const float4*)&Ss[kk][tc * 8 + 4];
            float sv[8] = {s0.x, s0.y, s0.z, s0.w, s1.x, s1.y, s1.z, s1.w};
            #pragma unroll
            for (int c = 0; c < 8; c++) {
                acc[0][c] += a0 * sv[c];
                acc[1][c] += a1 * sv[c];
                acc[2][c] += a2 * sv[c];
                acc[3][c] += a3 * sv[c];
            }
        }
        __syncthreads();
    }

    #pragma unroll
    for (int r = 0; r < 4; r++) {
        float4 v0 = {acc[r][0], acc[r][1], acc[r][2], acc[r][3]};
        float4 v1 = {acc[r][4], acc[r][5], acc[r][6], acc[r][7]};
        *(float4*)&out[(tr * 4 + r) * N_ + tc * 8]     = v0;
        *(float4*)&out[(tr * 4 + r) * N_ + tc * 8 + 4] = v1;
    }
}

// ----------------------------------------------------------------------------
// Projection: y[b,t] = bias + Hm[64,512] @ Z[512,128]
// Reduction index r = (e*4 + k)*64 + f ; Z rows: k==0 -> x[b,t], else g_tap[k-1].
// Chunked over 16 x 32 reduction rows; within a chunk (e,k) are constant.
// ----------------------------------------------------------------------------
__global__ __launch_bounds__(256) void proj_kernel(
    const float* __restrict__ x, const float* __restrict__ H,
    const float* __restrict__ bias, float* __restrict__ y)
{
    int idx = blockIdx.x;            // b*T + t
    int t = idx & (T_ - 1);
    int b = idx >> 6;

    int tid = threadIdx.x;
    int tc = tid & 15;
    int tr = tid >> 4;

    __shared__ float Hs[F_][33];
    __shared__ float Zs[32][N_ + 4];

    float acc[4][8];
    #pragma unroll
    for (int r = 0; r < 4; r++)
        #pragma unroll
        for (int c = 0; c < 8; c++) acc[r][c] = 0.f;

    for (int cc = 0; cc < 16; cc++) {
        int e  = cc >> 3;            // red/256
        int k  = (cc >> 1) & 3;      // (red/64)%4
        int f0 = (cc & 1) * 32;      // red%64 base

        const float* zp = (k == 0)
            ? x + ((b * T_ + t) * F_ + f0) * N_
            : &g_tap[k - 1][(((b * T_ + t) * E_ + e) * F_ + f0) * N_];

        // Load H chunk: Hs[o][j] = H[o*512 + cc*32 + j]  (coalesced)
        {
            int j = tid & 31, o0 = tid >> 5;
            #pragma unroll
            for (int i = 0; i < 8; i++)
                Hs[o0 + i * 8][j] = H[(o0 + i * 8) * 512 + cc * 32 + j];
        }
        // Load Z chunk: Zs[j][n] = zp[j*128 + n]  (coalesced)
        {
            int n = tid & 127, j0 = tid >> 7;
            #pragma unroll
            for (int i = 0; i < 16; i++)
                Zs[j0 + i * 2][n] = zp[(j0 + i * 2) * N_ + n];
        }
        __syncthreads();

        #pragma unroll
        for (int kk = 0; kk < 32; kk++) {
            float a0 = Hs[tr * 4 + 0][kk];
            float a1 = Hs[tr * 4 + 1][kk];
            float a2 = Hs[tr * 4 + 2][kk];
            float a3 = Hs[tr * 4 + 3][kk];
            float4 s0 = *(const float4*)&Zs[kk][tc * 8];
            float4 s1 = *(const float4*)&Zs[kk][tc * 8 + 4];
            float sv[8] = {s0.x, s0.y, s0.z, s0.w, s1.x, s1.y, s1.z, s1.w};
            #pragma unroll
            for (int c = 0; c < 8; c++) {
                acc[0][c] += a0 * sv[c];
                acc[1][c] += a1 * sv[c];
                acc[2][c] += a2 * sv[c];
                acc[3][c] += a3 * sv[c];
            }
        }
        __syncthreads();
    }

    float* yp = y + ((b * T_ + t) * F_) * N_;
    #pragma unroll
    for (int r = 0; r < 4; r++) {
        float bv = bias[tr * 4 + r];
        float4 v0 = {acc[r][0] + bv, acc[r][1] + bv, acc[r][2] + bv, acc[r][3] + bv};
        float4 v1 = {acc[r][4] + bv, acc[r][5] + bv, acc[r][6] + bv, acc[r][7] + bv};
        *(float4*)&yp[(tr * 4 + r) * N_ + tc * 8]     = v0;
        *(float4*)&yp[(tr * 4 + r) * N_ + tc * 8 + 4] = v1;
    }
}

// ----------------------------------------------------------------------------
// Inputs (metadata order): x [B,T,F,N] f32, S [B,T,E,N,N] f32,
//                          H [F_out,E,K,F_in] f32, bias [F_out,1] f32
// Output: y [B,T,F_out,N] f32
// ----------------------------------------------------------------------------
extern "C" void kernel_launch(void* const* d_in, const int* in_sizes, int n_in,
                              void* d_out, int out_size)
{
    const float* x    = (const float*)d_in[0];
    const float* S    = (const float*)d_in[1];
    const float* H    = (const float*)d_in[2];
    const float* bias = (const float*)d_in[3];
    float* y = (float*)d_out;

    // Three sequential diffusion passes build A1, A2, A3 (cross-launch deps
    // ordered by the stream).
    for (int pass = 0; pass < 3; pass++)
        diffuse_kernel<<<B_ * T_ * E_, 256>>>(x, S, pass);

    proj_kernel<<<B_ * T_, 256>>>(x, H, bias, y);
}

// round 3
// speedup vs baseline: 2.2988x; 2.2988x over previous
#include <cuda_runtime.h>
#include <cuda_bf16.h>
#include <cstdint>

#define B_ 16
#define T_ 64
#define E_ 2
#define F_ 64
#define N_ 128
#define TAPSZ (B_*T_*E_*F_*N_)

__device__ float g_tap[3][TAPSZ];

// ---------------------------------------------------------------------------
// helpers
// ---------------------------------------------------------------------------
__device__ __forceinline__ uint32_t pack_hi2(float a, float b) {
    uint32_t ua = (uint32_t)__bfloat16_as_ushort(__float2bfloat16(a));
    uint32_t ub = (uint32_t)__bfloat16_as_ushort(__float2bfloat16(b));
    return (ub << 16) | ua;                 // low 16 = first (even-k) element
}
__device__ __forceinline__ uint32_t pack_lo2(float a, float b) {
    __nv_bfloat16 ha = __float2bfloat16(a);
    __nv_bfloat16 hb = __float2bfloat16(b);
    float ra = a - __bfloat162float(ha);
    float rb = b - __bfloat162float(hb);
    uint32_t ua = (uint32_t)__bfloat16_as_ushort(__float2bfloat16(ra));
    uint32_t ub = (uint32_t)__bfloat16_as_ushort(__float2bfloat16(rb));
    return (ub << 16) | ua;
}

#define MMA_BF16(c, a0, a1, a2, a3, b0, b1)                                   \
    asm volatile(                                                             \
        "mma.sync.aligned.m16n8k16.row.col.f32.bf16.bf16.f32 "                \
        "{%0,%1,%2,%3}, {%4,%5,%6,%7}, {%8,%9}, {%0,%1,%2,%3};"               \
        : "+f"((c)[0]), "+f"((c)[1]), "+f"((c)[2]), "+f"((c)[3])              \
        : "r"(a0), "r"(a1), "r"(a2), "r"(a3), "r"(b0), "r"(b1))

// ---------------------------------------------------------------------------
// Diffusion: out[f][n] = sum_j in[f][j] * S[j][n]    ([64,128] @ [128,128])
// 256 threads = 8 warps; warp (wm, wn): rows 16*wm..+15, cols 64*wn..+63.
// smem: A hi/lo packed bf16x2 along k (u32 [64][68]),
//       B transposed hi/lo (u32 [128][68]):  Bt[n][kp] = (S[2kp][n], S[2kp+1][n])
// Padded stride 68 words -> fragment loads are bank-conflict-free.
// ---------------------------------------------------------------------------
#define DAP 68
#define D_AHI 0
#define D_ALO (64*DAP)
#define D_BHI (2*64*DAP)
#define D_BLO (2*64*DAP + 128*DAP)
#define D_SMEM_W (2*64*DAP + 2*128*DAP)          // 26112 words = 104448 B

__global__ void __launch_bounds__(256) diffuse_mma(
    const float* __restrict__ x, const float* __restrict__ S, int pass)
{
    extern __shared__ uint32_t sm[];
    int idx = blockIdx.x;
    int e = idx & 1, t = (idx >> 1) & 63, b = idx >> 7;
    int tid = threadIdx.x;

    float* out = &g_tap[pass][(((b * T_ + t) * E_ + e) * F_) * N_];
    if (t == 0) {
        float4 z4 = make_float4(0.f, 0.f, 0.f, 0.f);
        for (int i = tid; i < F_ * N_ / 4; i += 256) ((float4*)out)[i] = z4;
        return;
    }

    const float* inp = (pass == 0)
        ? x + ((b * T_ + (t - 1)) * F_) * N_
        : &g_tap[pass - 1][(((b * T_ + (t - 1)) * E_ + e) * F_) * N_];
    const float* Sp = S + (size_t)((b * T_ + t) * E_ + e) * N_ * N_;

    // A fill: 64 rows x 64 packed-k
    for (int i = tid; i < 64 * 64; i += 256) {
        int r = i >> 6, kp = i & 63;
        float2 v = *(const float2*)(inp + r * N_ + 2 * kp);
        sm[D_AHI + r * DAP + kp] = pack_hi2(v.x, v.y);
        sm[D_ALO + r * DAP + kp] = pack_lo2(v.x, v.y);
    }
    // B fill (transpose): 128 n x 64 packed-k
    for (int i = tid; i < 128 * 64; i += 256) {
        int n = i & 127, kp = i >> 7;
        float va = Sp[(2 * kp) * N_ + n];
        float vb = Sp[(2 * kp + 1) * N_ + n];
        sm[D_BHI + n * DAP + kp] = pack_hi2(va, vb);
        sm[D_BLO + n * DAP + kp] = pack_lo2(va, vb);
    }
    __syncthreads();

    int wid = tid >> 5, lane = tid & 31;
    int wm = wid & 3, wn = wid >> 2;
    int ra = lane >> 2, ca = lane & 3;

    float acc[8][4];
    #pragma unroll
    for (int nt = 0; nt < 8; nt++)
        #pragma unroll
        for (int j = 0; j < 4; j++) acc[nt][j] = 0.f;

    #pragma unroll
    for (int k = 0; k < 8; k++) {
        int ab = D_AHI + (16 * wm + ra) * DAP + k * 8 + ca;
        uint32_t ah0 = sm[ab],            ah1 = sm[ab + 8 * DAP];
        uint32_t ah2 = sm[ab + 4],        ah3 = sm[ab + 8 * DAP + 4];
        int al = ab + (D_ALO - D_AHI);
        uint32_t al0 = sm[al],            al1 = sm[al + 8 * DAP];
        uint32_t al2 = sm[al + 4],        al3 = sm[al + 8 * DAP + 4];
        #pragma unroll
        for (int nt = 0; nt < 8; nt++) {
            int bb = D_BHI + (64 * wn + nt * 8 + ra) * DAP + k * 8 + ca;
            uint32_t bh0 = sm[bb], bh1 = sm[bb + 4];
            uint32_t bl0 = sm[bb + (D_BLO - D_BHI)], bl1 = sm[bb + (D_BLO - D_BHI) + 4];
            MMA_BF16(acc[nt], ah0, ah1, ah2, ah3, bh0, bh1);
            MMA_BF16(acc[nt], ah0, ah1, ah2, ah3, bl0, bl1);
            MMA_BF16(acc[nt], al0, al1, al2, al3, bh0, bh1);
        }
    }

    int r0 = 16 * wm + ra;
    #pragma unroll
    for (int nt = 0; nt < 8; nt++) {
        int c = 64 * wn + nt * 8 + 2 * ca;
        *(float2*)(out + r0 * N_ + c)       = make_float2(acc[nt][0], acc[nt][1]);
        *(float2*)(out + (r0 + 8) * N_ + c) = make_float2(acc[nt][2], acc[nt][3]);
    }
}

// ---------------------------------------------------------------------------
// Projection: y[o][n] = bias[o] + sum_r Hm[o][r] * Z[r][n],  r=(e*4+k)*64+f
// 8 chunks of 64 reduction rows; acc lives in registers across chunks.
// ---------------------------------------------------------------------------
#define PAP 36
#define P_AHI 0
#define P_ALO (64*PAP)
#define P_BHI (2*64*PAP)
#define P_BLO (2*64*PAP + 128*PAP)
#define P_SMEM_W (2*64*PAP + 2*128*PAP)          // 13824 words = 55296 B

__global__ void __launch_bounds__(256) proj_mma(
    const float* __restrict__ x, const float* __restrict__ H,
    const float* __restrict__ bias, float* __restrict__ y)
{
    extern __shared__ uint32_t sm[];
    int idx = blockIdx.x;
    int t = idx & 63, b = idx >> 6;
    int tid = threadIdx.x;
    int wid = tid >> 5, lane = tid & 31;
    int wm = wid & 3, wn = wid >> 2;
    int ra = lane >> 2, ca = lane & 3;

    float acc[8][4];
    #pragma unroll
    for (int nt = 0; nt < 8; nt++)
        #pragma unroll
        for (int j = 0; j < 4; j++) acc[nt][j] = 0.f;

    for (int cc = 0; cc < 8; cc++) {
        int e = cc >> 2, k = cc & 3;
        const float* zp = (k == 0)
            ? x + ((b * T_ + t) * F_) * N_
            : &g_tap[k - 1][(((b * T_ + t) * E_ + e) * F_) * N_];

        __syncthreads();
        // A chunk: H[o][cc*64 + f], 64 x 32 packed
        for (int i = tid; i < 64 * 32; i += 256) {
            int o = i >> 5, kp = i & 31;
            float2 v = *(const float2*)(H + o * 512 + cc * 64 + 2 * kp);
            sm[P_AHI + o * PAP + kp] = pack_hi2(v.x, v.y);
            sm[P_ALO + o * PAP + kp] = pack_lo2(v.x, v.y);
        }
        // B chunk (transpose): 128 n x 32 packed
        for (int i = tid; i < 128 * 32; i += 256) {
            int n = i & 127, kp = i >> 7;
            float va = zp[(2 * kp) * N_ + n];
            float vb = zp[(2 * kp + 1) * N_ + n];
            sm[P_BHI + n * PAP + kp] = pack_hi2(va, vb);
            sm[P_BLO + n * PAP + kp] = pack_lo2(va, vb);
        }
        __syncthreads();

        #pragma unroll
        for (int kk = 0; kk < 4; kk++) {
            int ab = P_AHI + (16 * wm + ra) * PAP + kk * 8 + ca;
            uint32_t ah0 = sm[ab],     ah1 = sm[ab + 8 * PAP];
            uint32_t ah2 = sm[ab + 4], ah3 = sm[ab + 8 * PAP + 4];
            int al = ab + (P_ALO - P_AHI);
            uint32_t al0 = sm[al],     al1 = sm[al + 8 * PAP];
            uint32_t al2 = sm[al + 4], al3 = sm[al + 8 * PAP + 4];
            #pragma unroll
            for (int nt = 0; nt < 8; nt++) {
                int bb = P_BHI + (64 * wn + nt * 8 + ra) * PAP + kk * 8 + ca;
                uint32_t bh0 = sm[bb], bh1 = sm[bb + 4];
                uint32_t bl0 = sm[bb + (P_BLO - P_BHI)], bl1 = sm[bb + (P_BLO - P_BHI) + 4];
                MMA_BF16(acc[nt], ah0, ah1, ah2, ah3, bh0, bh1);
                MMA_BF16(acc[nt], ah0, ah1, ah2, ah3, bl0, bl1);
                MMA_BF16(acc[nt], al0, al1, al2, al3, bh0, bh1);
            }
        }
    }

    float* yp = y + ((size_t)(b * T_ + t) * F_) * N_;
    int r0 = 16 * wm + ra;
    float bv0 = bias[r0], bv1 = bias[r0 + 8];
    #pragma unroll
    for (int nt = 0; nt < 8; nt++) {
        int c = 64 * wn + nt * 8 + 2 * ca;
        *(float2*)(yp + r0 * N_ + c)       = make_float2(acc[nt][0] + bv0, acc[nt][1] + bv0);
        *(float2*)(yp + (r0 + 8) * N_ + c) = make_float2(acc[nt][2] + bv1, acc[nt][3] + bv1);
    }
}

// ---------------------------------------------------------------------------
extern "C" void kernel_launch(void* const* d_in, const int* in_sizes, int n_in,
                              void* d_out, int out_size)
{
    const float* x    = (const float*)d_in[0];
    const float* S    = (const float*)d_in[1];
    const float* H    = (const float*)d_in[2];
    const float* bias = (const float*)d_in[3];
    float* y = (float*)d_out;

    cudaFuncSetAttribute(diffuse_mma, cudaFuncAttributeMaxDynamicSharedMemorySize,
                         D_SMEM_W * 4);
    cudaFuncSetAttribute(proj_mma, cudaFuncAttributeMaxDynamicSharedMemorySize,
                         P_SMEM_W * 4);

    for (int pass = 0; pass < 3; pass++)
        diffuse_mma<<<B_ * T_ * E_, 256, D_SMEM_W * 4>>>(x, S, pass);

    proj_mma<<<B_ * T_, 256, P_SMEM_W * 4>>>(x, H, bias, y);
}